// round 11
// baseline (speedup 1.0000x reference)
#include <cuda_runtime.h>
#include <cuda_fp16.h>
#include <math.h>
#include <stdint.h>

#define HH 512
#define WW 512
#define CC 64
#define HW (HH*WW)
#define PW 516                 // padded H/W (reflect pad 2 materialized)
#define MPX 128                // pixels per CTA tile
#define NTHR 128

// smem layout (bytes) — double-buffered stage
#define ASTRIDE 144            // 64 ch * 2B payload, padded (ldmatrix conflict-free)
#define APX 132                // staged pixels per row (128 + halo 4)
#define SM_A    0
#define SM_B    (APX * ASTRIDE)                 // 19008
#define BSLOT   (64 * ASTRIDE)                  // 9216 per tap
#define SM_BUF  (SM_B + 3 * BSLOT)              // 46656 per stage buffer
#define SM_TOTAL (2 * SM_BUF)                   // 93312
#define EPI_STRIDE 65                           // floats; epi aliases smem (33280 B)

typedef unsigned short ushort_t;

// ------------------------- device globals (no allocation) -------------------
__device__ __half g_xh[(size_t)PW * PW * CC];   // x, padded NHWC fp16
__device__ __half g_oh[(size_t)PW * PW * CC];   // x_ori, padded NHWC fp16
__device__ ushort_t g_w[2 * 9 * 4096];          // [conv][tap][ci*64+co] fp16
__device__ unsigned char g_md_[HW];

// ------------------------- helpers ------------------------------------------
__device__ __forceinline__ int reflect512(int i) {
    i = abs(i);
    return min(i, 1022 - i);
}
__device__ __forceinline__ float gelu_exact(float v) {
    return 0.5f * v * (1.0f + erff(v * 0.70710678118654752f));
}
__device__ __forceinline__ uint32_t smem_u32(const void* p) {
    uint32_t a;
    asm("{ .reg .u64 t; cvta.to.shared.u64 t, %1; cvt.u32.u64 %0, t; }" : "=r"(a) : "l"(p));
    return a;
}
__device__ __forceinline__ void cp16(uint32_t dst, const void* src) {
    asm volatile("cp.async.cg.shared.global [%0], [%1], 16;" :: "r"(dst), "l"(src));
}
__device__ __forceinline__ void cp_commit() {
    asm volatile("cp.async.commit_group;");
}
template <int N>
__device__ __forceinline__ void cp_wait() {
    asm volatile("cp.async.wait_group %0;" :: "n"(N));
}
__device__ __forceinline__ void ldsm4(uint32_t (&r)[4], uint32_t addr) {
    asm volatile("ldmatrix.sync.aligned.m8n8.x4.shared.b16 {%0,%1,%2,%3}, [%4];"
                 : "=r"(r[0]), "=r"(r[1]), "=r"(r[2]), "=r"(r[3]) : "r"(addr));
}
__device__ __forceinline__ void ldsm4t(uint32_t (&r)[4], uint32_t addr) {
    asm volatile("ldmatrix.sync.aligned.m8n8.x4.trans.shared.b16 {%0,%1,%2,%3}, [%4];"
                 : "=r"(r[0]), "=r"(r[1]), "=r"(r[2]), "=r"(r[3]) : "r"(addr));
}
__device__ __forceinline__ void mma16816(float (&d)[4], const uint32_t (&a)[4],
                                         uint32_t b0, uint32_t b1) {
    asm volatile(
        "mma.sync.aligned.m16n8k16.row.col.f32.f16.f16.f32 "
        "{%0,%1,%2,%3}, {%4,%5,%6,%7}, {%8,%9}, {%0,%1,%2,%3};"
        : "+f"(d[0]), "+f"(d[1]), "+f"(d[2]), "+f"(d[3])
        : "r"(a[0]), "r"(a[1]), "r"(a[2]), "r"(a[3]), "r"(b0), "r"(b1));
}

// ------------------------- prepasses -----------------------------------------
__global__ void md_kernel(const float* __restrict__ mask) {
    int x = blockIdx.x * 32 + threadIdx.x;
    int y = blockIdx.y * 8 + threadIdx.y;
    float m = 0.0f;
    #pragma unroll
    for (int dy = -2; dy <= 2; dy++) {
        int yy = y + dy;
        if (yy < 0 || yy >= HH) continue;
        #pragma unroll
        for (int dx = -2; dx <= 2; dx++) {
            int xx = x + dx;
            if (xx < 0 || xx >= WW) continue;
            m = fmaxf(m, mask[yy * WW + xx]);
        }
    }
    g_md_[y * WW + x] = (m > 0.5f) ? 1 : 0;
}

// x (NCHW fp32) -> padded NHWC fp16
__global__ void prep_x(const float* __restrict__ x) {
    __shared__ ushort_t sh[32][66];
    const int yp  = blockIdx.y;
    const int xp0 = blockIdx.x * 32;
    const int tid = threadIdx.x;
    const int warp = tid >> 5, lane = tid & 31;
    const int ry = reflect512(yp - 2);
    const int xp = xp0 + lane;
    const int rx = reflect512((xp < PW ? xp : PW - 1) - 2);
    #pragma unroll
    for (int q = 0; q < 8; q++) {
        int ci = warp * 8 + q;
        float v = x[(size_t)ci * HW + (size_t)ry * WW + rx];
        sh[lane][ci] = __half_as_ushort(__float2half_rn(v));
    }
    __syncthreads();
    const int jj = tid >> 3, c0 = (tid & 7) * 8;
    const int xpw = xp0 + jj;
    if (xpw < PW) {
        size_t base = ((size_t)yp * PW + xpw) * 64 + c0;
        uint32_t a[4];
        #pragma unroll
        for (int i = 0; i < 4; i++)
            a[i] = (uint32_t)sh[jj][c0 + 2*i] | ((uint32_t)sh[jj][c0 + 2*i + 1] << 16);
        *reinterpret_cast<uint4*>(&g_xh[base]) = make_uint4(a[0], a[1], a[2], a[3]);
    }
}

// weights -> [conv][tap][ci][co] fp16
__global__ void prep_w(const float* __restrict__ w1, const float* __restrict__ w2) {
    int idx = blockIdx.x * 256 + threadIdx.x;
    if (idx >= 2 * 9 * 64 * 64) return;
    int conv = idx / 36864;
    int r    = idx % 36864;
    int tap  = r / 4096;
    int r2   = r % 4096;
    int co = r2 >> 6, ci = r2 & 63;
    const float* w = conv ? w2 : w1;
    float v = w[(co * 64 + ci) * 9 + tap];
    g_w[(size_t)(conv * 9 + tap) * 4096 + ci * 64 + co] =
        __half_as_ushort(__float2half_rn(v));
}

// fill reflect-padding ring of g_oh from interior (after conv1)
__global__ void ring_fix() {
    int p = blockIdx.x * 256 + threadIdx.x;
    if (p >= PW * PW) return;
    int yp = p / PW, xp = p % PW;
    if (yp >= 2 && yp < PW - 2 && xp >= 2 && xp < PW - 2) return;
    int sy = reflect512(yp - 2) + 2;
    int sx = reflect512(xp - 2) + 2;
    size_t d = (size_t)p * 64;
    size_t s = ((size_t)sy * PW + sx) * 64;
    uint4* dh = reinterpret_cast<uint4*>(&g_oh[d]);
    const uint4* shp = reinterpret_cast<const uint4*>(&g_oh[s]);
    #pragma unroll
    for (int i = 0; i < 8; i++) dh[i] = shp[i];
}

// ------------------------- conv via warp MMA (fp16, pipelined) ---------------
// MODE 1: input g_xh -> g_oh = fp16( md ? gelu(conv+b1) : x )
// MODE 2: input g_oh -> d_out[sd] = gelu(conv+b2) + x
template <int MODE>
__global__ void __launch_bounds__(NTHR, 2) conv_mma(
    const float* __restrict__ xres,
    const float* __restrict__ bias,
    const float* __restrict__ mask,
    float* __restrict__ out)
{
    extern __shared__ __align__(16) char smem[];
    const uint32_t sb = smem_u32(smem);
    const int tid = threadIdx.x;
    const int warp = tid >> 5, lane = tid & 31;
    const int x0 = blockIdx.x * MPX;
    const int y  = blockIdx.y;

    const __half* xin = (MODE == 1) ? g_xh : g_oh;
    const ushort_t* wbase = g_w + (size_t)((MODE == 1) ? 0 : 9) * 4096;

    const uint32_t a_off = (uint32_t)(lane & 15) * ASTRIDE + (uint32_t)(lane >> 4) * 16;
    const uint32_t b_off = (uint32_t)((lane & 7) + ((lane >> 3) & 1) * 8) * ASTRIDE
                         + (uint32_t)(lane >> 4) * 16;

    // stage row dy(dyi) into buffer `buf`
    auto stage = [&](int dyi, uint32_t bufbase) {
        const char* asrc = reinterpret_cast<const char*>(
            &xin[((size_t)(y + 2 * dyi) * PW + x0) * 64]);
        #pragma unroll
        for (int it = 0; it < (APX * 8 + NTHR - 1) / NTHR; it++) {
            int i = tid + it * NTHR;
            if (i < APX * 8) {
                int px = i >> 3, seg = i & 7;
                cp16(bufbase + SM_A + px * ASTRIDE + seg * 16, asrc + i * 16);
            }
        }
        const char* bsrc = reinterpret_cast<const char*>(wbase + (size_t)(3 * dyi) * 4096);
        #pragma unroll
        for (int it = 0; it < (3 * 512) / NTHR; it++) {
            int i = tid + it * NTHR;
            int slot = i >> 9;
            int rem  = i & 511;
            int ci = rem >> 3, seg = rem & 7;
            cp16(bufbase + SM_B + slot * BSLOT + ci * ASTRIDE + seg * 16, bsrc + i * 16);
        }
        cp_commit();
    };

    float acc[2][8][4];
    #pragma unroll
    for (int mt = 0; mt < 2; mt++)
        #pragma unroll
        for (int nt = 0; nt < 8; nt++)
            #pragma unroll
            for (int i = 0; i < 4; i++) acc[mt][nt][i] = 0.0f;

    // prologue: stage dy0 into buffer 0
    stage(0, sb);

    #pragma unroll
    for (int dyi = 0; dyi < 3; dyi++) {
        const uint32_t cur = sb + (uint32_t)(dyi & 1) * SM_BUF;
        __syncthreads();                 // everyone done reading buffer being restaged
        if (dyi < 2) {
            stage(dyi + 1, sb + (uint32_t)((dyi + 1) & 1) * SM_BUF);
            cp_wait<1>();                // current buffer's group complete
        } else {
            cp_wait<0>();
        }
        __syncthreads();                 // current buffer visible to all

        #pragma unroll
        for (int dxi = 0; dxi < 3; dxi++) {
            const uint32_t am0 = cur + SM_A + (uint32_t)(32 * warp + 2 * dxi) * ASTRIDE + a_off;
            const uint32_t bb  = cur + SM_B + (uint32_t)dxi * BSLOT + b_off;
            #pragma unroll
            for (int kc = 0; kc < 64; kc += 16) {
                uint32_t ah0[4], ah1[4];
                ldsm4(ah0, am0 + kc * 2);
                ldsm4(ah1, am0 + 16 * ASTRIDE + kc * 2);
                const uint32_t bbase = bb + (uint32_t)kc * ASTRIDE;
                #pragma unroll
                for (int nb = 0; nb < 4; nb++) {
                    uint32_t bh[4];
                    ldsm4t(bh, bbase + nb * 32);
                    mma16816(acc[0][2*nb],   ah0, bh[0], bh[1]);
                    mma16816(acc[0][2*nb+1], ah0, bh[2], bh[3]);
                    mma16816(acc[1][2*nb],   ah1, bh[0], bh[1]);
                    mma16816(acc[1][2*nb+1], ah1, bh[2], bh[3]);
                }
            }
        }
    }

    // ---- epilogue: fragments -> smem (pixel-major), then write out ----
    __syncthreads();
    float* sepi = reinterpret_cast<float*>(smem);
    #pragma unroll
    for (int mt = 0; mt < 2; mt++) {
        const int r = 32 * warp + 16 * mt + (lane >> 2);
        #pragma unroll
        for (int nt = 0; nt < 8; nt++) {
            const int c = 8 * nt + 2 * (lane & 3);
            sepi[r * EPI_STRIDE + c]           = acc[mt][nt][0];
            sepi[r * EPI_STRIDE + c + 1]       = acc[mt][nt][1];
            sepi[(r + 8) * EPI_STRIDE + c]     = acc[mt][nt][2];
            sepi[(r + 8) * EPI_STRIDE + c + 1] = acc[mt][nt][3];
        }
    }
    __syncwarp();

    const int m = tid;                 // local pixel (warp w owns px 32w..32w+31)
    const int x = x0 + m;
    const int p = y * WW + x;
    const float* arow = &sepi[m * EPI_STRIDE];

    if (MODE == 1) {
        const bool md = (g_md_[p] != 0);
        const size_t ob = ((size_t)(y + 2) * PW + (x + 2)) * 64;
        uint4* dh = reinterpret_cast<uint4*>(&g_oh[ob]);
        if (md) {
            uint32_t oh[32];
            #pragma unroll
            for (int j = 0; j < 32; j++) {
                const int c0 = 2 * j;
                float v0 = gelu_exact(arow[c0]     + __ldg(&bias[c0]));
                float v1 = gelu_exact(arow[c0 + 1] + __ldg(&bias[c0 + 1]));
                oh[j] = (uint32_t)__half_as_ushort(__float2half_rn(v0))
                      | ((uint32_t)__half_as_ushort(__float2half_rn(v1)) << 16);
            }
            #pragma unroll
            for (int i = 0; i < 8; i++)
                dh[i] = make_uint4(oh[4*i], oh[4*i+1], oh[4*i+2], oh[4*i+3]);
        } else {
            const uint4* shp = reinterpret_cast<const uint4*>(&g_xh[ob]);
            #pragma unroll
            for (int i = 0; i < 8; i++) dh[i] = shp[i];
        }
    } else {
        if (mask[p] > 0.5f) {
            #pragma unroll 8
            for (int c = 0; c < 64; c++) {
                const size_t o = (size_t)c * HW + p;
                out[o] = gelu_exact(arow[c] + __ldg(&bias[c])) + xres[o];
            }
        }
    }
}

// ------------------------- depthwise path ------------------------------------
__global__ void dw_kernel(
    const float* __restrict__ x,
    const float* __restrict__ w3,
    const float* __restrict__ b3,
    const float* __restrict__ mask,
    float* __restrict__ out)
{
    int gx = blockIdx.x * 256 + threadIdx.x;
    int gy = blockIdx.y;
    int c  = blockIdx.z;
    int p  = gy * WW + gx;
    if (mask[p] > 0.5f) return;

    const float* wc = w3 + c * 9;
    const float* xc = x + (size_t)c * HW;
    float a = 0.0f;
    #pragma unroll
    for (int k = 0; k < 9; k++) {
        int yy = reflect512(gy + (k / 3) * 2 - 2);
        int xx = reflect512(gx + (k % 3) * 2 - 2);
        a = fmaf(xc[yy * WW + xx], wc[k], a);
    }
    out[(size_t)c * HW + p] = gelu_exact(a + b3[c]) + xc[p];
}

// ------------------------- launch --------------------------------------------
extern "C" void kernel_launch(void* const* d_in, const int* in_sizes, int n_in,
                              void* d_out, int out_size) {
    const float* x    = (const float*)d_in[0];
    const float* mask = (const float*)d_in[1];
    const float* w1   = (const float*)d_in[2];
    const float* b1   = (const float*)d_in[3];
    const float* w2   = (const float*)d_in[4];
    const float* b2   = (const float*)d_in[5];
    const float* w3   = (const float*)d_in[6];
    const float* b3   = (const float*)d_in[7];
    float* out = (float*)d_out;

    static bool attr_set = false;
    if (!attr_set) {
        cudaFuncSetAttribute(conv_mma<1>,
            cudaFuncAttributeMaxDynamicSharedMemorySize, SM_TOTAL);
        cudaFuncSetAttribute(conv_mma<2>,
            cudaFuncAttributeMaxDynamicSharedMemorySize, SM_TOTAL);
        attr_set = true;
    }

    md_kernel<<<dim3(WW / 32, HH / 8), dim3(32, 8)>>>(mask);
    prep_w<<<(2 * 9 * 64 * 64 + 255) / 256, 256>>>(w1, w2);
    prep_x<<<dim3((PW + 31) / 32, PW), 256>>>(x);

    dim3 cgrid(WW / MPX, HH);   // 4 x 512

    conv_mma<1><<<cgrid, NTHR, SM_TOTAL>>>(x, b1, mask, out);
    ring_fix<<<(PW * PW + 255) / 256, 256>>>();
    conv_mma<2><<<cgrid, NTHR, SM_TOTAL>>>(x, b2, mask, out);

    dw_kernel<<<dim3(WW / 256, HH, CC), 256>>>(x, w3, b3, mask, out);
}

// round 12
// speedup vs baseline: 1.1681x; 1.1681x over previous
#include <cuda_runtime.h>
#include <cuda_fp16.h>
#include <math.h>
#include <stdint.h>

#define HH 512
#define WW 512
#define CC 64
#define HW (HH*WW)
#define PW 516                 // padded H/W (reflect pad 2 materialized)
#define MPX 128                // pixels per CTA tile
#define NTHR 128

// smem layout (bytes) — single stage buffer + w3/b3 slab
#define ASTRIDE 144            // 64 ch * 2B payload, padded (ldmatrix conflict-free)
#define APX 132                // staged pixels per row (128 + halo 4)
#define SM_A    0
#define SM_B    (APX * ASTRIDE)                 // 19008
#define BSLOT   (64 * ASTRIDE)                  // 9216 per tap
#define SM_W3   (SM_B + 3 * BSLOT)              // 46656 (9*64 fp32 = 2304)
#define SM_B3   (SM_W3 + 2304)                  // 48960 (64 fp32 = 256)
#define SM_TOTAL (SM_B3 + 256)                  // 49216
#define EPI_STRIDE 65                           // floats; epi aliases smem [0, 33280)

typedef unsigned short ushort_t;

// ------------------------- device globals (no allocation) -------------------
__device__ __half g_xh[(size_t)PW * PW * CC];   // x, padded NHWC fp16
__device__ __half g_oh[(size_t)PW * PW * CC];   // x_ori, padded NHWC fp16
__device__ ushort_t g_w[2 * 9 * 4096];          // [conv][tap][ci*64+co] fp16
__device__ unsigned char g_md_[HW];

// ------------------------- helpers ------------------------------------------
__device__ __forceinline__ int reflect512(int i) {
    i = abs(i);
    return min(i, 1022 - i);
}
__device__ __forceinline__ float gelu_exact(float v) {
    return 0.5f * v * (1.0f + erff(v * 0.70710678118654752f));
}
__device__ __forceinline__ uint32_t smem_u32(const void* p) {
    uint32_t a;
    asm("{ .reg .u64 t; cvta.to.shared.u64 t, %1; cvt.u32.u64 %0, t; }" : "=r"(a) : "l"(p));
    return a;
}
__device__ __forceinline__ void cp16(uint32_t dst, const void* src) {
    asm volatile("cp.async.cg.shared.global [%0], [%1], 16;" :: "r"(dst), "l"(src));
}
__device__ __forceinline__ void cp_commit_wait() {
    asm volatile("cp.async.commit_group;");
    asm volatile("cp.async.wait_group 0;");
}
__device__ __forceinline__ void ldsm4(uint32_t (&r)[4], uint32_t addr) {
    asm volatile("ldmatrix.sync.aligned.m8n8.x4.shared.b16 {%0,%1,%2,%3}, [%4];"
                 : "=r"(r[0]), "=r"(r[1]), "=r"(r[2]), "=r"(r[3]) : "r"(addr));
}
__device__ __forceinline__ void ldsm4t(uint32_t (&r)[4], uint32_t addr) {
    asm volatile("ldmatrix.sync.aligned.m8n8.x4.trans.shared.b16 {%0,%1,%2,%3}, [%4];"
                 : "=r"(r[0]), "=r"(r[1]), "=r"(r[2]), "=r"(r[3]) : "r"(addr));
}
__device__ __forceinline__ void mma16816(float (&d)[4], const uint32_t (&a)[4],
                                         uint32_t b0, uint32_t b1) {
    asm volatile(
        "mma.sync.aligned.m16n8k16.row.col.f32.f16.f16.f32 "
        "{%0,%1,%2,%3}, {%4,%5,%6,%7}, {%8,%9}, {%0,%1,%2,%3};"
        : "+f"(d[0]), "+f"(d[1]), "+f"(d[2]), "+f"(d[3])
        : "r"(a[0]), "r"(a[1]), "r"(a[2]), "r"(a[3]), "r"(b0), "r"(b1));
}

// ------------------------- prepasses -----------------------------------------
__global__ void md_kernel(const float* __restrict__ mask) {
    int x = blockIdx.x * 32 + threadIdx.x;
    int y = blockIdx.y * 8 + threadIdx.y;
    float m = 0.0f;
    #pragma unroll
    for (int dy = -2; dy <= 2; dy++) {
        int yy = y + dy;
        if (yy < 0 || yy >= HH) continue;
        #pragma unroll
        for (int dx = -2; dx <= 2; dx++) {
            int xx = x + dx;
            if (xx < 0 || xx >= WW) continue;
            m = fmaxf(m, mask[yy * WW + xx]);
        }
    }
    g_md_[y * WW + x] = (m > 0.5f) ? 1 : 0;
}

// x (NCHW fp32) -> padded NHWC fp16
__global__ void prep_x(const float* __restrict__ x) {
    __shared__ ushort_t sh[32][66];
    const int yp  = blockIdx.y;
    const int xp0 = blockIdx.x * 32;
    const int tid = threadIdx.x;
    const int warp = tid >> 5, lane = tid & 31;
    const int ry = reflect512(yp - 2);
    const int xp = xp0 + lane;
    const int rx = reflect512((xp < PW ? xp : PW - 1) - 2);
    #pragma unroll
    for (int q = 0; q < 8; q++) {
        int ci = warp * 8 + q;
        float v = x[(size_t)ci * HW + (size_t)ry * WW + rx];
        sh[lane][ci] = __half_as_ushort(__float2half_rn(v));
    }
    __syncthreads();
    const int jj = tid >> 3, c0 = (tid & 7) * 8;
    const int xpw = xp0 + jj;
    if (xpw < PW) {
        size_t base = ((size_t)yp * PW + xpw) * 64 + c0;
        uint32_t a[4];
        #pragma unroll
        for (int i = 0; i < 4; i++)
            a[i] = (uint32_t)sh[jj][c0 + 2*i] | ((uint32_t)sh[jj][c0 + 2*i + 1] << 16);
        *reinterpret_cast<uint4*>(&g_xh[base]) = make_uint4(a[0], a[1], a[2], a[3]);
    }
}

// weights -> [conv][tap][ci][co] fp16
__global__ void prep_w(const float* __restrict__ w1, const float* __restrict__ w2) {
    int idx = blockIdx.x * 256 + threadIdx.x;
    if (idx >= 2 * 9 * 64 * 64) return;
    int conv = idx / 36864;
    int r    = idx % 36864;
    int tap  = r / 4096;
    int r2   = r % 4096;
    int co = r2 >> 6, ci = r2 & 63;
    const float* w = conv ? w2 : w1;
    float v = w[(co * 64 + ci) * 9 + tap];
    g_w[(size_t)(conv * 9 + tap) * 4096 + ci * 64 + co] =
        __half_as_ushort(__float2half_rn(v));
}

// fill reflect-padding ring of g_oh from interior (after conv1)
__global__ void ring_fix() {
    int p = blockIdx.x * 256 + threadIdx.x;
    if (p >= PW * PW) return;
    int yp = p / PW, xp = p % PW;
    if (yp >= 2 && yp < PW - 2 && xp >= 2 && xp < PW - 2) return;
    int sy = reflect512(yp - 2) + 2;
    int sx = reflect512(xp - 2) + 2;
    size_t d = (size_t)p * 64;
    size_t s = ((size_t)sy * PW + sx) * 64;
    uint4* dh = reinterpret_cast<uint4*>(&g_oh[d]);
    const uint4* shp = reinterpret_cast<const uint4*>(&g_oh[s]);
    #pragma unroll
    for (int i = 0; i < 8; i++) dh[i] = shp[i];
}

// ------------------------- conv via warp MMA (fp16, single pass) -------------
// MODE 1: input g_xh -> g_oh = fp16( md ? gelu(conv+b1) : x )
// MODE 2: input g_oh -> d_out = sd ? gelu(conv+b2)+x : gelu(dw(x)+b3)+x
template <int MODE>
__global__ void __launch_bounds__(NTHR, 3) conv_mma(
    const float* __restrict__ xres,
    const float* __restrict__ bias,
    const float* __restrict__ mask,
    const float* __restrict__ w3,
    const float* __restrict__ b3,
    float* __restrict__ out)
{
    extern __shared__ __align__(16) char smem[];
    const uint32_t sb = smem_u32(smem);
    const int tid = threadIdx.x;
    const int warp = tid >> 5, lane = tid & 31;
    const int x0 = blockIdx.x * MPX;
    const int y  = blockIdx.y;

    const __half* xin = (MODE == 1) ? g_xh : g_oh;
    const ushort_t* wbase = g_w + (size_t)((MODE == 1) ? 0 : 9) * 4096;

    // MODE 2: stage depthwise weights/bias once (region untouched by A/B/epi)
    if (MODE == 2) {
        float* w3s = reinterpret_cast<float*>(smem + SM_W3);
        float* b3s = reinterpret_cast<float*>(smem + SM_B3);
        if (tid < 64) {
            #pragma unroll
            for (int t = 0; t < 9; t++) w3s[t * 64 + tid] = w3[tid * 9 + t];
            b3s[tid] = b3[tid];
        }
    }

    const uint32_t a_off = (uint32_t)(lane & 15) * ASTRIDE + (uint32_t)(lane >> 4) * 16;
    const uint32_t b_off = (uint32_t)((lane & 7) + ((lane >> 3) & 1) * 8) * ASTRIDE
                         + (uint32_t)(lane >> 4) * 16;

    float acc[2][8][4];
    #pragma unroll
    for (int mt = 0; mt < 2; mt++)
        #pragma unroll
        for (int nt = 0; nt < 8; nt++)
            #pragma unroll
            for (int i = 0; i < 4; i++) acc[mt][nt][i] = 0.0f;

    for (int dyi = 0; dyi < 3; dyi++) {
        __syncthreads();   // A/B buffers safe to overwrite (also covers w3 staging)
        // ---- stage A: padded row y + 2*dyi, APX px (cp.async) ----
        {
            const char* src = reinterpret_cast<const char*>(
                &xin[((size_t)(y + 2 * dyi) * PW + x0) * 64]);
            #pragma unroll
            for (int it = 0; it < (APX * 8 + NTHR - 1) / NTHR; it++) {
                int i = tid + it * NTHR;
                if (i < APX * 8) {
                    int px = i >> 3, seg = i & 7;
                    cp16(sb + SM_A + px * ASTRIDE + seg * 16, src + i * 16);
                }
            }
        }
        // ---- stage B: 3 taps of this dy-row (cp.async) ----
        {
            const char* src = reinterpret_cast<const char*>(wbase + (size_t)(3 * dyi) * 4096);
            #pragma unroll
            for (int it = 0; it < (3 * 512) / NTHR; it++) {
                int i = tid + it * NTHR;
                int slot = i >> 9;
                int rem  = i & 511;
                int ci = rem >> 3, seg = rem & 7;
                cp16(sb + SM_B + slot * BSLOT + ci * ASTRIDE + seg * 16, src + i * 16);
            }
        }
        cp_commit_wait();
        __syncthreads();

        #pragma unroll
        for (int dxi = 0; dxi < 3; dxi++) {
            const uint32_t am0 = sb + SM_A + (uint32_t)(32 * warp + 2 * dxi) * ASTRIDE + a_off;
            const uint32_t bb  = sb + SM_B + (uint32_t)dxi * BSLOT + b_off;
            #pragma unroll
            for (int kc = 0; kc < 64; kc += 16) {
                uint32_t ah0[4], ah1[4];
                ldsm4(ah0, am0 + kc * 2);
                ldsm4(ah1, am0 + 16 * ASTRIDE + kc * 2);
                const uint32_t bbase = bb + (uint32_t)kc * ASTRIDE;
                #pragma unroll
                for (int nb = 0; nb < 4; nb++) {
                    uint32_t bh[4];
                    ldsm4t(bh, bbase + nb * 32);
                    mma16816(acc[0][2*nb],   ah0, bh[0], bh[1]);
                    mma16816(acc[0][2*nb+1], ah0, bh[2], bh[3]);
                    mma16816(acc[1][2*nb],   ah1, bh[0], bh[1]);
                    mma16816(acc[1][2*nb+1], ah1, bh[2], bh[3]);
                }
            }
        }
    }

    // ---- epilogue: fragments -> smem (pixel-major), then write out ----
    __syncthreads();
    float* sepi = reinterpret_cast<float*>(smem);
    #pragma unroll
    for (int mt = 0; mt < 2; mt++) {
        const int r = 32 * warp + 16 * mt + (lane >> 2);
        #pragma unroll
        for (int nt = 0; nt < 8; nt++) {
            const int c = 8 * nt + 2 * (lane & 3);
            sepi[r * EPI_STRIDE + c]           = acc[mt][nt][0];
            sepi[r * EPI_STRIDE + c + 1]       = acc[mt][nt][1];
            sepi[(r + 8) * EPI_STRIDE + c]     = acc[mt][nt][2];
            sepi[(r + 8) * EPI_STRIDE + c + 1] = acc[mt][nt][3];
        }
    }
    __syncwarp();

    const int m = tid;                 // local pixel (warp w owns px 32w..32w+31)
    const int x = x0 + m;
    const int p = y * WW + x;
    const float* arow = &sepi[m * EPI_STRIDE];

    if (MODE == 1) {
        const bool md = (g_md_[p] != 0);
        const size_t ob = ((size_t)(y + 2) * PW + (x + 2)) * 64;
        uint4* dh = reinterpret_cast<uint4*>(&g_oh[ob]);
        if (md) {
            uint32_t oh[32];
            #pragma unroll
            for (int j = 0; j < 32; j++) {
                const int c0 = 2 * j;
                float v0 = gelu_exact(arow[c0]     + __ldg(&bias[c0]));
                float v1 = gelu_exact(arow[c0 + 1] + __ldg(&bias[c0 + 1]));
                oh[j] = (uint32_t)__half_as_ushort(__float2half_rn(v0))
                      | ((uint32_t)__half_as_ushort(__float2half_rn(v1)) << 16);
            }
            #pragma unroll
            for (int i = 0; i < 8; i++)
                dh[i] = make_uint4(oh[4*i], oh[4*i+1], oh[4*i+2], oh[4*i+3]);
        } else {
            const uint4* shp = reinterpret_cast<const uint4*>(&g_xh[ob]);
            #pragma unroll
            for (int i = 0; i < 8; i++) dh[i] = shp[i];
        }
    } else {
        const bool sd = mask[p] > 0.5f;
        if (sd) {
            #pragma unroll 8
            for (int c = 0; c < 64; c++) {
                const size_t o = (size_t)c * HW + p;
                out[o] = gelu_exact(arow[c] + __ldg(&bias[c])) + xres[o];
            }
        } else {
            // fused depthwise conv on ORIGINAL x (fp16 NHWC padded, ring valid)
            const float* w3s = reinterpret_cast<const float*>(smem + SM_W3);
            const float* b3s = reinterpret_cast<const float*>(smem + SM_B3);
            uint32_t pos[9];
            #pragma unroll
            for (int t = 0; t < 9; t++)
                pos[t] = (uint32_t)((y + 2 * (t / 3)) * PW + (x + 2 * (t % 3))) * 64u;
            #pragma unroll
            for (int ch = 0; ch < 64; ch += 16) {
                float a16[16];
                #pragma unroll
                for (int i = 0; i < 16; i++) a16[i] = 0.0f;
                #pragma unroll
                for (int t = 0; t < 9; t++) {
                    uint4 v0 = *reinterpret_cast<const uint4*>(&g_xh[(size_t)pos[t] + ch]);
                    uint4 v1 = *reinterpret_cast<const uint4*>(&g_xh[(size_t)pos[t] + ch + 8]);
                    const __half2* h0 = reinterpret_cast<const __half2*>(&v0);
                    const __half2* h1 = reinterpret_cast<const __half2*>(&v1);
                    const float* wrow = &w3s[t * 64 + ch];
                    #pragma unroll
                    for (int j = 0; j < 4; j++) {
                        float2 f = __half22float2(h0[j]);
                        float2 wv = *reinterpret_cast<const float2*>(&wrow[2 * j]);
                        a16[2*j]     = fmaf(f.x, wv.x, a16[2*j]);
                        a16[2*j + 1] = fmaf(f.y, wv.y, a16[2*j + 1]);
                    }
                    #pragma unroll
                    for (int j = 0; j < 4; j++) {
                        float2 f = __half22float2(h1[j]);
                        float2 wv = *reinterpret_cast<const float2*>(&wrow[8 + 2 * j]);
                        a16[8 + 2*j]     = fmaf(f.x, wv.x, a16[8 + 2*j]);
                        a16[8 + 2*j + 1] = fmaf(f.y, wv.y, a16[8 + 2*j + 1]);
                    }
                }
                #pragma unroll
                for (int j = 0; j < 16; j++) {
                    const int c = ch + j;
                    const size_t o = (size_t)c * HW + p;
                    out[o] = gelu_exact(a16[j] + b3s[c]) + xres[o];
                }
            }
        }
    }
}

// ------------------------- launch --------------------------------------------
extern "C" void kernel_launch(void* const* d_in, const int* in_sizes, int n_in,
                              void* d_out, int out_size) {
    const float* x    = (const float*)d_in[0];
    const float* mask = (const float*)d_in[1];
    const float* w1   = (const float*)d_in[2];
    const float* b1   = (const float*)d_in[3];
    const float* w2   = (const float*)d_in[4];
    const float* b2   = (const float*)d_in[5];
    const float* w3   = (const float*)d_in[6];
    const float* b3   = (const float*)d_in[7];
    float* out = (float*)d_out;

    static bool attr_set = false;
    if (!attr_set) {
        cudaFuncSetAttribute(conv_mma<1>,
            cudaFuncAttributeMaxDynamicSharedMemorySize, SM_TOTAL);
        cudaFuncSetAttribute(conv_mma<2>,
            cudaFuncAttributeMaxDynamicSharedMemorySize, SM_TOTAL);
        attr_set = true;
    }

    md_kernel<<<dim3(WW / 32, HH / 8), dim3(32, 8)>>>(mask);
    prep_w<<<(2 * 9 * 64 * 64 + 255) / 256, 256>>>(w1, w2);
    prep_x<<<dim3((PW + 31) / 32, PW), 256>>>(x);

    dim3 cgrid(WW / MPX, HH);   // 4 x 512

    conv_mma<1><<<cgrid, NTHR, SM_TOTAL>>>(x, b1, mask, w3, b3, out);
    ring_fix<<<(PW * PW + 255) / 256, 256>>>();
    conv_mma<2><<<cgrid, NTHR, SM_TOTAL>>>(x, b2, mask, w3, b3, out);
}

// round 13
// speedup vs baseline: 1.2675x; 1.0850x over previous
#include <cuda_runtime.h>
#include <cuda_fp16.h>
#include <math.h>
#include <stdint.h>

#define HH 512
#define WW 512
#define CC 64
#define HW (HH*WW)
#define PW 516                 // padded H/W (reflect pad 2 materialized)
#define MPX 64                 // pixels per CTA tile
#define NTHR 128

// smem layout (bytes)
#define ASTRIDE 144            // 64 ch * 2B payload, padded (ldmatrix conflict-free)
#define APX 68                 // staged pixels per row (64 + halo 4)
#define SM_A    0
#define SM_B    (APX * ASTRIDE)                 // 9792
#define BSLOT   (64 * ASTRIDE)                  // 9216 per tap
#define SM_W3   (SM_B + 3 * BSLOT)              // 37440 (9*64 fp32)
#define SM_B3   (SM_W3 + 2304)                  // 39744
#define SM_TOTAL (SM_B3 + 256)                  // 40000
#define EPI_STRIDE 65                           // floats; sepi aliases [0,16640)
#define SM_MASK 16640                           // 5*68 floats (MODE1 only)

typedef unsigned short ushort_t;

// ------------------------- device globals (no allocation) -------------------
__device__ __half g_xh[(size_t)PW * PW * CC];   // x, padded NHWC fp16
__device__ __half g_oh[(size_t)PW * PW * CC];   // x_ori, padded NHWC fp16
__device__ ushort_t g_w[2 * 9 * 4096];          // [conv][tap][ci*64+co] fp16

// ------------------------- helpers ------------------------------------------
__device__ __forceinline__ int reflect512(int i) {
    i = abs(i);
    return min(i, 1022 - i);
}
__device__ __forceinline__ float gelu_exact(float v) {
    return 0.5f * v * (1.0f + erff(v * 0.70710678118654752f));
}
__device__ __forceinline__ uint32_t smem_u32(const void* p) {
    uint32_t a;
    asm("{ .reg .u64 t; cvta.to.shared.u64 t, %1; cvt.u32.u64 %0, t; }" : "=r"(a) : "l"(p));
    return a;
}
__device__ __forceinline__ void cp16(uint32_t dst, const void* src) {
    asm volatile("cp.async.cg.shared.global [%0], [%1], 16;" :: "r"(dst), "l"(src));
}
__device__ __forceinline__ void cp_commit_wait() {
    asm volatile("cp.async.commit_group;");
    asm volatile("cp.async.wait_group 0;");
}
__device__ __forceinline__ void ldsm4(uint32_t (&r)[4], uint32_t addr) {
    asm volatile("ldmatrix.sync.aligned.m8n8.x4.shared.b16 {%0,%1,%2,%3}, [%4];"
                 : "=r"(r[0]), "=r"(r[1]), "=r"(r[2]), "=r"(r[3]) : "r"(addr));
}
__device__ __forceinline__ void ldsm4t(uint32_t (&r)[4], uint32_t addr) {
    asm volatile("ldmatrix.sync.aligned.m8n8.x4.trans.shared.b16 {%0,%1,%2,%3}, [%4];"
                 : "=r"(r[0]), "=r"(r[1]), "=r"(r[2]), "=r"(r[3]) : "r"(addr));
}
__device__ __forceinline__ void mma16816(float (&d)[4], const uint32_t (&a)[4],
                                         uint32_t b0, uint32_t b1) {
    asm volatile(
        "mma.sync.aligned.m16n8k16.row.col.f32.f16.f16.f32 "
        "{%0,%1,%2,%3}, {%4,%5,%6,%7}, {%8,%9}, {%0,%1,%2,%3};"
        : "+f"(d[0]), "+f"(d[1]), "+f"(d[2]), "+f"(d[3])
        : "r"(a[0]), "r"(a[1]), "r"(a[2]), "r"(a[3]), "r"(b0), "r"(b1));
}

// ------------------------- prepasses -----------------------------------------
// x (NCHW fp32) -> padded NHWC fp16
__global__ void prep_x(const float* __restrict__ x) {
    __shared__ ushort_t sh[32][66];
    const int yp  = blockIdx.y;
    const int xp0 = blockIdx.x * 32;
    const int tid = threadIdx.x;
    const int warp = tid >> 5, lane = tid & 31;
    const int ry = reflect512(yp - 2);
    const int xp = xp0 + lane;
    const int rx = reflect512((xp < PW ? xp : PW - 1) - 2);
    #pragma unroll
    for (int q = 0; q < 8; q++) {
        int ci = warp * 8 + q;
        float v = x[(size_t)ci * HW + (size_t)ry * WW + rx];
        sh[lane][ci] = __half_as_ushort(__float2half_rn(v));
    }
    __syncthreads();
    const int jj = tid >> 3, c0 = (tid & 7) * 8;
    const int xpw = xp0 + jj;
    if (xpw < PW) {
        size_t base = ((size_t)yp * PW + xpw) * 64 + c0;
        uint32_t a[4];
        #pragma unroll
        for (int i = 0; i < 4; i++)
            a[i] = (uint32_t)sh[jj][c0 + 2*i] | ((uint32_t)sh[jj][c0 + 2*i + 1] << 16);
        *reinterpret_cast<uint4*>(&g_xh[base]) = make_uint4(a[0], a[1], a[2], a[3]);
    }
}

// weights -> [conv][tap][ci][co] fp16
__global__ void prep_w(const float* __restrict__ w1, const float* __restrict__ w2) {
    int idx = blockIdx.x * 256 + threadIdx.x;
    if (idx >= 2 * 9 * 64 * 64) return;
    int conv = idx / 36864;
    int r    = idx % 36864;
    int tap  = r / 4096;
    int r2   = r % 4096;
    int co = r2 >> 6, ci = r2 & 63;
    const float* w = conv ? w2 : w1;
    float v = w[(co * 64 + ci) * 9 + tap];
    g_w[(size_t)(conv * 9 + tap) * 4096 + ci * 64 + co] =
        __half_as_ushort(__float2half_rn(v));
}

// ------------------------- conv via warp MMA (fp16, single pass) -------------
// Warp tile: 32 px x 32 co. CTA: 64 px, 4 warps (px-half x co-half).
// MODE 1: g_xh -> g_oh = fp16( md ? gelu(conv+b1) : x )  [+ ring mirror + fused md]
// MODE 2: g_oh -> d_out = sd ? gelu(conv+b2)+x : gelu(dw(x)+b3)+x
template <int MODE>
__global__ void __launch_bounds__(NTHR, 5) conv_mma(
    const float* __restrict__ xres,
    const float* __restrict__ bias,
    const float* __restrict__ mask,
    const float* __restrict__ w3,
    const float* __restrict__ b3,
    float* __restrict__ out)
{
    extern __shared__ __align__(16) char smem[];
    const uint32_t sb = smem_u32(smem);
    const int tid = threadIdx.x;
    const int warp = tid >> 5, lane = tid & 31;
    const int ph = warp >> 1;         // pixel half (0: px 0-31, 1: px 32-63)
    const int ch = warp & 1;          // co half (0: co 0-31, 1: co 32-63)
    const int x0 = blockIdx.x * MPX;
    const int y  = blockIdx.y;

    const __half* xin = (MODE == 1) ? g_xh : g_oh;
    const ushort_t* wbase = g_w + (size_t)((MODE == 1) ? 0 : 9) * 4096;

    // MODE 2: stage depthwise weights/bias once
    if (MODE == 2) {
        float* w3s = reinterpret_cast<float*>(smem + SM_W3);
        float* b3s = reinterpret_cast<float*>(smem + SM_B3);
        if (tid < 64) {
            #pragma unroll
            for (int t = 0; t < 9; t++) w3s[t * 64 + tid] = w3[tid * 9 + t];
            b3s[tid] = b3[tid];
        }
    }

    const uint32_t a_off = (uint32_t)(lane & 15) * ASTRIDE + (uint32_t)(lane >> 4) * 16;
    const uint32_t b_off = (uint32_t)((lane & 7) + ((lane >> 3) & 1) * 8) * ASTRIDE
                         + (uint32_t)(lane >> 4) * 16;

    float acc[2][4][4];
    #pragma unroll
    for (int mt = 0; mt < 2; mt++)
        #pragma unroll
        for (int nt = 0; nt < 4; nt++)
            #pragma unroll
            for (int i = 0; i < 4; i++) acc[mt][nt][i] = 0.0f;

    for (int dyi = 0; dyi < 3; dyi++) {
        __syncthreads();
        // ---- stage A: padded row y + 2*dyi, APX px ----
        {
            const char* src = reinterpret_cast<const char*>(
                &xin[((size_t)(y + 2 * dyi) * PW + x0) * 64]);
            #pragma unroll
            for (int it = 0; it < 5; it++) {
                int i = tid + it * NTHR;
                if (i < APX * 8) {
                    int px = i >> 3, seg = i & 7;
                    cp16(sb + SM_A + px * ASTRIDE + seg * 16, src + i * 16);
                }
            }
        }
        // ---- stage B: 3 taps of this dy-row ----
        {
            const char* src = reinterpret_cast<const char*>(wbase + (size_t)(3 * dyi) * 4096);
            #pragma unroll
            for (int it = 0; it < 12; it++) {
                int i = tid + it * NTHR;
                int slot = i >> 9;
                int rem  = i & 511;
                int ci = rem >> 3, seg = rem & 7;
                cp16(sb + SM_B + slot * BSLOT + ci * ASTRIDE + seg * 16, src + i * 16);
            }
        }
        cp_commit_wait();
        __syncthreads();

        #pragma unroll
        for (int dxi = 0; dxi < 3; dxi++) {
            const uint32_t am0 = sb + SM_A + (uint32_t)(32 * ph + 2 * dxi) * ASTRIDE + a_off;
            const uint32_t bb  = sb + SM_B + (uint32_t)dxi * BSLOT + (uint32_t)ch * 64 + b_off;
            #pragma unroll
            for (int kc = 0; kc < 64; kc += 16) {
                uint32_t ah0[4], ah1[4];
                ldsm4(ah0, am0 + kc * 2);
                ldsm4(ah1, am0 + 16 * ASTRIDE + kc * 2);
                const uint32_t bbase = bb + (uint32_t)kc * ASTRIDE;
                uint32_t bh0[4], bh1[4];
                ldsm4t(bh0, bbase);
                ldsm4t(bh1, bbase + 32);
                mma16816(acc[0][0], ah0, bh0[0], bh0[1]);
                mma16816(acc[0][1], ah0, bh0[2], bh0[3]);
                mma16816(acc[0][2], ah0, bh1[0], bh1[1]);
                mma16816(acc[0][3], ah0, bh1[2], bh1[3]);
                mma16816(acc[1][0], ah1, bh0[0], bh0[1]);
                mma16816(acc[1][1], ah1, bh0[2], bh0[3]);
                mma16816(acc[1][2], ah1, bh1[0], bh1[1]);
                mma16816(acc[1][3], ah1, bh1[2], bh1[3]);
            }
        }
    }

    // ---- epilogue: fragments -> smem (pixel-major) + (MODE1) mask slab ----
    __syncthreads();
    float* sepi = reinterpret_cast<float*>(smem);
    #pragma unroll
    for (int mt = 0; mt < 2; mt++) {
        const int r = 32 * ph + 16 * mt + (lane >> 2);
        #pragma unroll
        for (int nt = 0; nt < 4; nt++) {
            const int c = 32 * ch + 8 * nt + 2 * (lane & 3);
            sepi[r * EPI_STRIDE + c]           = acc[mt][nt][0];
            sepi[r * EPI_STRIDE + c + 1]       = acc[mt][nt][1];
            sepi[(r + 8) * EPI_STRIDE + c]     = acc[mt][nt][2];
            sepi[(r + 8) * EPI_STRIDE + c + 1] = acc[mt][nt][3];
        }
    }
    if (MODE == 1) {
        // stage clipped 5x68 mask window (md = 5x5 max, SAME padding)
        float* smask = reinterpret_cast<float*>(smem + SM_MASK);
        for (int i = tid; i < 5 * 68; i += NTHR) {
            int r = i / 68, c = i - r * 68;
            int gy = y - 2 + r, gx = x0 - 2 + c;
            smask[i] = ((unsigned)gy < HH && (unsigned)gx < WW)
                     ? mask[gy * WW + gx] : 0.0f;
        }
    }
    __syncthreads();

    const int m   = tid & 63;          // local pixel
    const int chb = (tid >> 6) * 32;   // channel base (0 or 32)
    const int x = x0 + m;
    const int p = y * WW + x;
    const float* arow = &sepi[m * EPI_STRIDE];

    if (MODE == 1) {
        // fused mask dilation
        const float* smask = reinterpret_cast<const float*>(smem + SM_MASK);
        float mx = 0.0f;
        #pragma unroll
        for (int r = 0; r < 5; r++)
            #pragma unroll
            for (int c = 0; c < 5; c++)
                mx = fmaxf(mx, smask[r * 68 + m + c]);
        const bool md = mx > 0.5f;

        const size_t ob = ((size_t)(y + 2) * PW + (x + 2)) * 64 + chb;
        uint4 v[4];
        if (md) {
            #pragma unroll
            for (int i = 0; i < 4; i++) {
                uint32_t w[4];
                #pragma unroll
                for (int q = 0; q < 4; q++) {
                    const int c0 = chb + 8 * i + 2 * q;
                    float v0 = gelu_exact(arow[c0]     + __ldg(&bias[c0]));
                    float v1 = gelu_exact(arow[c0 + 1] + __ldg(&bias[c0 + 1]));
                    w[q] = (uint32_t)__half_as_ushort(__float2half_rn(v0))
                         | ((uint32_t)__half_as_ushort(__float2half_rn(v1)) << 16);
                }
                v[i] = make_uint4(w[0], w[1], w[2], w[3]);
            }
        } else {
            const uint4* shp = reinterpret_cast<const uint4*>(&g_xh[ob]);
            #pragma unroll
            for (int i = 0; i < 4; i++) v[i] = shp[i];
        }
        uint4* dh = reinterpret_cast<uint4*>(&g_oh[ob]);
        #pragma unroll
        for (int i = 0; i < 4; i++) dh[i] = v[i];

        // fused reflect-ring mirror (replaces ring_fix kernel)
        int yr = -1, xr = -1;
        if (y == 1 || y == 2) yr = 2 - y;
        else if (y == 509 || y == 510) yr = 1024 - y;
        if (x == 1 || x == 2) xr = 2 - x;
        else if (x == 509 || x == 510) xr = 1024 - x;
        if (yr >= 0) {
            uint4* d = reinterpret_cast<uint4*>(&g_oh[((size_t)yr * PW + (x + 2)) * 64 + chb]);
            #pragma unroll
            for (int i = 0; i < 4; i++) d[i] = v[i];
        }
        if (xr >= 0) {
            uint4* d = reinterpret_cast<uint4*>(&g_oh[((size_t)(y + 2) * PW + xr) * 64 + chb]);
            #pragma unroll
            for (int i = 0; i < 4; i++) d[i] = v[i];
        }
        if (yr >= 0 && xr >= 0) {
            uint4* d = reinterpret_cast<uint4*>(&g_oh[((size_t)yr * PW + xr) * 64 + chb]);
            #pragma unroll
            for (int i = 0; i < 4; i++) d[i] = v[i];
        }
    } else {
        const bool sd = mask[p] > 0.5f;
        if (sd) {
            #pragma unroll 8
            for (int j = 0; j < 32; j++) {
                const int c = chb + j;
                const size_t o = (size_t)c * HW + p;
                out[o] = gelu_exact(arow[c] + __ldg(&bias[c])) + xres[o];
            }
        } else {
            // fused depthwise conv on ORIGINAL x (fp16 NHWC padded, ring valid)
            const float* w3s = reinterpret_cast<const float*>(smem + SM_W3);
            const float* b3s = reinterpret_cast<const float*>(smem + SM_B3);
            uint32_t pos[9];
            #pragma unroll
            for (int t = 0; t < 9; t++)
                pos[t] = (uint32_t)((y + 2 * (t / 3)) * PW + (x + 2 * (t % 3))) * 64u;
            #pragma unroll
            for (int cc2 = 0; cc2 < 32; cc2 += 16) {
                const int cbase = chb + cc2;
                float a16[16];
                #pragma unroll
                for (int i = 0; i < 16; i++) a16[i] = 0.0f;
                #pragma unroll
                for (int t = 0; t < 9; t++) {
                    uint4 v0 = *reinterpret_cast<const uint4*>(&g_xh[(size_t)pos[t] + cbase]);
                    uint4 v1 = *reinterpret_cast<const uint4*>(&g_xh[(size_t)pos[t] + cbase + 8]);
                    const __half2* h0 = reinterpret_cast<const __half2*>(&v0);
                    const __half2* h1 = reinterpret_cast<const __half2*>(&v1);
                    const float* wrow = &w3s[t * 64 + cbase];
                    #pragma unroll
                    for (int j = 0; j < 4; j++) {
                        float2 f = __half22float2(h0[j]);
                        float2 wv = *reinterpret_cast<const float2*>(&wrow[2 * j]);
                        a16[2*j]     = fmaf(f.x, wv.x, a16[2*j]);
                        a16[2*j + 1] = fmaf(f.y, wv.y, a16[2*j + 1]);
                    }
                    #pragma unroll
                    for (int j = 0; j < 4; j++) {
                        float2 f = __half22float2(h1[j]);
                        float2 wv = *reinterpret_cast<const float2*>(&wrow[8 + 2 * j]);
                        a16[8 + 2*j]     = fmaf(f.x, wv.x, a16[8 + 2*j]);
                        a16[8 + 2*j + 1] = fmaf(f.y, wv.y, a16[8 + 2*j + 1]);
                    }
                }
                #pragma unroll
                for (int j = 0; j < 16; j++) {
                    const int c = cbase + j;
                    const size_t o = (size_t)c * HW + p;
                    out[o] = gelu_exact(a16[j] + b3s[c]) + xres[o];
                }
            }
        }
    }
}

// ------------------------- launch --------------------------------------------
extern "C" void kernel_launch(void* const* d_in, const int* in_sizes, int n_in,
                              void* d_out, int out_size) {
    const float* x    = (const float*)d_in[0];
    const float* mask = (const float*)d_in[1];
    const float* w1   = (const float*)d_in[2];
    const float* b1   = (const float*)d_in[3];
    const float* w2   = (const float*)d_in[4];
    const float* b2   = (const float*)d_in[5];
    const float* w3   = (const float*)d_in[6];
    const float* b3   = (const float*)d_in[7];
    float* out = (float*)d_out;

    static bool attr_set = false;
    if (!attr_set) {
        cudaFuncSetAttribute(conv_mma<1>,
            cudaFuncAttributeMaxDynamicSharedMemorySize, SM_TOTAL);
        cudaFuncSetAttribute(conv_mma<2>,
            cudaFuncAttributeMaxDynamicSharedMemorySize, SM_TOTAL);
        attr_set = true;
    }

    prep_w<<<(2 * 9 * 64 * 64 + 255) / 256, 256>>>(w1, w2);
    prep_x<<<dim3((PW + 31) / 32, PW), 256>>>(x);

    dim3 cgrid(WW / MPX, HH);   // 8 x 512

    conv_mma<1><<<cgrid, NTHR, SM_TOTAL>>>(x, b1, mask, w3, b3, out);
    conv_mma<2><<<cgrid, NTHR, SM_TOTAL>>>(x, b2, mask, w3, b3, out);
}

// round 14
// speedup vs baseline: 1.2988x; 1.0247x over previous
#include <cuda_runtime.h>
#include <cuda_fp16.h>
#include <math.h>
#include <stdint.h>

#define HH 512
#define WW 512
#define CC 64
#define HW (HH*WW)
#define PW 516                 // padded H/W (reflect pad 2 materialized)
#define MPX 128                // pixels per CTA tile
#define NTHR 128

// smem layout (bytes)
#define ASTRIDE 144            // 64 ch * 2B payload, padded (ldmatrix conflict-free)
#define APX 132                // staged pixels per row (128 + halo 4)
#define SM_A    0
#define SM_B    (APX * ASTRIDE)                 // 19008
#define BSLOT   (64 * ASTRIDE)                  // 9216 per tap
#define SM_W3   (SM_B + 3 * BSLOT)              // 46656
#define SM_B3   (SM_W3 + 2304)                  // 48960
#define SM_TOTAL (SM_B3 + 256)                  // 49216
#define EPI_STRIDE 65                           // floats; sepi aliases [0, 33280)
#define SM_FLAG 33280                           // 128 bytes (MODE2 sd flags)
#define SM_MASK 33408                           // 5*132 floats (MODE1) -> ends 36048

typedef unsigned short ushort_t;

// ------------------------- device globals (no allocation) -------------------
__device__ __half g_xh[(size_t)PW * PW * CC];   // x, padded NHWC fp16
__device__ __half g_oh[(size_t)PW * PW * CC];   // x_ori, padded NHWC fp16
__device__ ushort_t g_w[2 * 9 * 4096];          // [conv][tap][ci*64+co] fp16

// ------------------------- helpers ------------------------------------------
__device__ __forceinline__ int reflect512(int i) {
    i = abs(i);
    return min(i, 1022 - i);
}
__device__ __forceinline__ float gelu_exact(float v) {
    return 0.5f * v * (1.0f + erff(v * 0.70710678118654752f));
}
__device__ __forceinline__ uint32_t smem_u32(const void* p) {
    uint32_t a;
    asm("{ .reg .u64 t; cvta.to.shared.u64 t, %1; cvt.u32.u64 %0, t; }" : "=r"(a) : "l"(p));
    return a;
}
__device__ __forceinline__ void cp16(uint32_t dst, const void* src) {
    asm volatile("cp.async.cg.shared.global [%0], [%1], 16;" :: "r"(dst), "l"(src));
}
__device__ __forceinline__ void cp_commit_wait() {
    asm volatile("cp.async.commit_group;");
    asm volatile("cp.async.wait_group 0;");
}
__device__ __forceinline__ void ldsm4(uint32_t (&r)[4], uint32_t addr) {
    asm volatile("ldmatrix.sync.aligned.m8n8.x4.shared.b16 {%0,%1,%2,%3}, [%4];"
                 : "=r"(r[0]), "=r"(r[1]), "=r"(r[2]), "=r"(r[3]) : "r"(addr));
}
__device__ __forceinline__ void ldsm4t(uint32_t (&r)[4], uint32_t addr) {
    asm volatile("ldmatrix.sync.aligned.m8n8.x4.trans.shared.b16 {%0,%1,%2,%3}, [%4];"
                 : "=r"(r[0]), "=r"(r[1]), "=r"(r[2]), "=r"(r[3]) : "r"(addr));
}
__device__ __forceinline__ void mma16816(float (&d)[4], const uint32_t (&a)[4],
                                         uint32_t b0, uint32_t b1) {
    asm volatile(
        "mma.sync.aligned.m16n8k16.row.col.f32.f16.f16.f32 "
        "{%0,%1,%2,%3}, {%4,%5,%6,%7}, {%8,%9}, {%0,%1,%2,%3};"
        : "+f"(d[0]), "+f"(d[1]), "+f"(d[2]), "+f"(d[3])
        : "r"(a[0]), "r"(a[1]), "r"(a[2]), "r"(a[3]), "r"(b0), "r"(b1));
}

// ------------------------- prepasses -----------------------------------------
// x (NCHW fp32) -> padded NHWC fp16
__global__ void prep_x(const float* __restrict__ x) {
    __shared__ ushort_t sh[32][66];
    const int yp  = blockIdx.y;
    const int xp0 = blockIdx.x * 32;
    const int tid = threadIdx.x;
    const int warp = tid >> 5, lane = tid & 31;
    const int ry = reflect512(yp - 2);
    const int xp = xp0 + lane;
    const int rx = reflect512((xp < PW ? xp : PW - 1) - 2);
    #pragma unroll
    for (int q = 0; q < 8; q++) {
        int ci = warp * 8 + q;
        float v = x[(size_t)ci * HW + (size_t)ry * WW + rx];
        sh[lane][ci] = __half_as_ushort(__float2half_rn(v));
    }
    __syncthreads();
    const int jj = tid >> 3, c0 = (tid & 7) * 8;
    const int xpw = xp0 + jj;
    if (xpw < PW) {
        size_t base = ((size_t)yp * PW + xpw) * 64 + c0;
        uint32_t a[4];
        #pragma unroll
        for (int i = 0; i < 4; i++)
            a[i] = (uint32_t)sh[jj][c0 + 2*i] | ((uint32_t)sh[jj][c0 + 2*i + 1] << 16);
        *reinterpret_cast<uint4*>(&g_xh[base]) = make_uint4(a[0], a[1], a[2], a[3]);
    }
}

// weights -> [conv][tap][ci][co] fp16
__global__ void prep_w(const float* __restrict__ w1, const float* __restrict__ w2) {
    int idx = blockIdx.x * 256 + threadIdx.x;
    if (idx >= 2 * 9 * 64 * 64) return;
    int conv = idx / 36864;
    int r    = idx % 36864;
    int tap  = r / 4096;
    int r2   = r % 4096;
    int co = r2 >> 6, ci = r2 & 63;
    const float* w = conv ? w2 : w1;
    float v = w[(co * 64 + ci) * 9 + tap];
    g_w[(size_t)(conv * 9 + tap) * 4096 + ci * 64 + co] =
        __half_as_ushort(__float2half_rn(v));
}

// ------------------------- conv via warp MMA (fp16, single pass) -------------
// Warp tile: 32 px x 64 co (R12 shape). CTA: 128 px, 4 warps.
// MODE 1: g_xh -> g_oh = fp16( md ? gelu(conv+b1) : x )  [fused md + ring mirror]
// MODE 2: g_oh -> d_out = sd ? gelu(conv+b2)+x : gelu(dw(x)+b3)+x  [coalesced dw]
template <int MODE>
__global__ void __launch_bounds__(NTHR, 3) conv_mma(
    const float* __restrict__ xres,
    const float* __restrict__ bias,
    const float* __restrict__ mask,
    const float* __restrict__ w3,
    const float* __restrict__ b3,
    float* __restrict__ out)
{
    extern __shared__ __align__(16) char smem[];
    const uint32_t sb = smem_u32(smem);
    const int tid = threadIdx.x;
    const int warp = tid >> 5, lane = tid & 31;
    const int x0 = blockIdx.x * MPX;
    const int y  = blockIdx.y;

    const __half* xin = (MODE == 1) ? g_xh : g_oh;
    const ushort_t* wbase = g_w + (size_t)((MODE == 1) ? 0 : 9) * 4096;

    // MODE 2: stage depthwise weights/bias once
    if (MODE == 2) {
        float* w3s = reinterpret_cast<float*>(smem + SM_W3);
        float* b3s = reinterpret_cast<float*>(smem + SM_B3);
        if (tid < 64) {
            #pragma unroll
            for (int t = 0; t < 9; t++) w3s[t * 64 + tid] = w3[tid * 9 + t];
            b3s[tid] = b3[tid];
        }
    }

    const uint32_t a_off = (uint32_t)(lane & 15) * ASTRIDE + (uint32_t)(lane >> 4) * 16;
    const uint32_t b_off = (uint32_t)((lane & 7) + ((lane >> 3) & 1) * 8) * ASTRIDE
                         + (uint32_t)(lane >> 4) * 16;

    float acc[2][8][4];
    #pragma unroll
    for (int mt = 0; mt < 2; mt++)
        #pragma unroll
        for (int nt = 0; nt < 8; nt++)
            #pragma unroll
            for (int i = 0; i < 4; i++) acc[mt][nt][i] = 0.0f;

    for (int dyi = 0; dyi < 3; dyi++) {
        __syncthreads();
        // ---- stage A: padded row y + 2*dyi, APX px ----
        {
            const char* src = reinterpret_cast<const char*>(
                &xin[((size_t)(y + 2 * dyi) * PW + x0) * 64]);
            #pragma unroll
            for (int it = 0; it < 9; it++) {
                int i = tid + it * NTHR;
                if (i < APX * 8) {
                    int px = i >> 3, seg = i & 7;
                    cp16(sb + SM_A + px * ASTRIDE + seg * 16, src + i * 16);
                }
            }
        }
        // ---- stage B: 3 taps of this dy-row ----
        {
            const char* src = reinterpret_cast<const char*>(wbase + (size_t)(3 * dyi) * 4096);
            #pragma unroll
            for (int it = 0; it < 12; it++) {
                int i = tid + it * NTHR;
                int slot = i >> 9;
                int rem  = i & 511;
                int ci = rem >> 3, seg = rem & 7;
                cp16(sb + SM_B + slot * BSLOT + ci * ASTRIDE + seg * 16, src + i * 16);
            }
        }
        cp_commit_wait();
        __syncthreads();

        #pragma unroll
        for (int dxi = 0; dxi < 3; dxi++) {
            const uint32_t am0 = sb + SM_A + (uint32_t)(32 * warp + 2 * dxi) * ASTRIDE + a_off;
            const uint32_t bb  = sb + SM_B + (uint32_t)dxi * BSLOT + b_off;
            #pragma unroll
            for (int kc = 0; kc < 64; kc += 16) {
                uint32_t ah0[4], ah1[4];
                ldsm4(ah0, am0 + kc * 2);
                ldsm4(ah1, am0 + 16 * ASTRIDE + kc * 2);
                const uint32_t bbase = bb + (uint32_t)kc * ASTRIDE;
                #pragma unroll
                for (int nb = 0; nb < 4; nb++) {
                    uint32_t bh[4];
                    ldsm4t(bh, bbase + nb * 32);
                    mma16816(acc[0][2*nb],   ah0, bh[0], bh[1]);
                    mma16816(acc[0][2*nb+1], ah0, bh[2], bh[3]);
                    mma16816(acc[1][2*nb],   ah1, bh[0], bh[1]);
                    mma16816(acc[1][2*nb+1], ah1, bh[2], bh[3]);
                }
            }
        }
    }

    // ---- epilogue: fragments -> smem (pixel-major) ----
    __syncthreads();
    float* sepi = reinterpret_cast<float*>(smem);
    #pragma unroll
    for (int mt = 0; mt < 2; mt++) {
        const int r = 32 * warp + 16 * mt + (lane >> 2);
        #pragma unroll
        for (int nt = 0; nt < 8; nt++) {
            const int c = 8 * nt + 2 * (lane & 3);
            sepi[r * EPI_STRIDE + c]           = acc[mt][nt][0];
            sepi[r * EPI_STRIDE + c + 1]       = acc[mt][nt][1];
            sepi[(r + 8) * EPI_STRIDE + c]     = acc[mt][nt][2];
            sepi[(r + 8) * EPI_STRIDE + c + 1] = acc[mt][nt][3];
        }
    }

    const int m = tid;                 // this thread's pixel
    const int x = x0 + m;
    const int p = y * WW + x;

    if (MODE == 1) {
        // fused mask dilation: stage clipped 5x132 mask window
        float* smask = reinterpret_cast<float*>(smem + SM_MASK);
        for (int i = tid; i < 5 * 132; i += NTHR) {
            int r = i / 132, c = i - r * 132;
            int gy = y - 2 + r, gx = x0 - 2 + c;
            smask[i] = ((unsigned)gy < HH && (unsigned)gx < WW)
                     ? mask[gy * WW + gx] : 0.0f;
        }
        __syncthreads();
        const float* arow = &sepi[m * EPI_STRIDE];
        float mx = 0.0f;
        #pragma unroll
        for (int r = 0; r < 5; r++)
            #pragma unroll
            for (int c = 0; c < 5; c++)
                mx = fmaxf(mx, smask[r * 132 + m + c]);
        const bool md = mx > 0.5f;

        const size_t ob = ((size_t)(y + 2) * PW + (x + 2)) * 64;
        uint4 v[8];
        if (md) {
            #pragma unroll
            for (int i = 0; i < 8; i++) {
                uint32_t w[4];
                #pragma unroll
                for (int q = 0; q < 4; q++) {
                    const int c0 = 8 * i + 2 * q;
                    float v0 = gelu_exact(arow[c0]     + __ldg(&bias[c0]));
                    float v1 = gelu_exact(arow[c0 + 1] + __ldg(&bias[c0 + 1]));
                    w[q] = (uint32_t)__half_as_ushort(__float2half_rn(v0))
                         | ((uint32_t)__half_as_ushort(__float2half_rn(v1)) << 16);
                }
                v[i] = make_uint4(w[0], w[1], w[2], w[3]);
            }
        } else {
            const uint4* shp = reinterpret_cast<const uint4*>(&g_xh[ob]);
            #pragma unroll
            for (int i = 0; i < 8; i++) v[i] = shp[i];
        }
        uint4* dh = reinterpret_cast<uint4*>(&g_oh[ob]);
        #pragma unroll
        for (int i = 0; i < 8; i++) dh[i] = v[i];

        // fused reflect-ring mirror
        int yr = -1, xr = -1;
        if (y == 1 || y == 2) yr = 2 - y;
        else if (y == 509 || y == 510) yr = 1024 - y;
        if (x == 1 || x == 2) xr = 2 - x;
        else if (x == 509 || x == 510) xr = 1024 - x;
        if (yr >= 0) {
            uint4* d = reinterpret_cast<uint4*>(&g_oh[((size_t)yr * PW + (x + 2)) * 64]);
            #pragma unroll
            for (int i = 0; i < 8; i++) d[i] = v[i];
        }
        if (xr >= 0) {
            uint4* d = reinterpret_cast<uint4*>(&g_oh[((size_t)(y + 2) * PW + xr) * 64]);
            #pragma unroll
            for (int i = 0; i < 8; i++) d[i] = v[i];
        }
        if (yr >= 0 && xr >= 0) {
            uint4* d = reinterpret_cast<uint4*>(&g_oh[((size_t)yr * PW + xr) * 64]);
            #pragma unroll
            for (int i = 0; i < 8; i++) d[i] = v[i];
        }
    } else {
        // ---- MODE 2: flags, coalesced dw into sepi at ~sd pixels, unified write
        unsigned char* sflag = reinterpret_cast<unsigned char*>(smem + SM_FLAG);
        const bool sd = mask[p] > 0.5f;
        sflag[m] = sd ? 1 : 0;
        __syncthreads();

        const float* w3s = reinterpret_cast<const float*>(smem + SM_W3);
        const float* b3s = reinterpret_cast<const float*>(smem + SM_B3);

        // cooperative dw: 8 threads per pixel (thread = (px, seg)); 16 px per pass
        const int seg = tid & 7;
        #pragma unroll
        for (int pass = 0; pass < 8; pass++) {
            const int px = pass * 16 + (tid >> 3);
            if (!sflag[px]) {
                const int gx2 = x0 + px;
                float a8[8];
                #pragma unroll
                for (int i = 0; i < 8; i++) a8[i] = 0.0f;
                #pragma unroll
                for (int t = 0; t < 9; t++) {
                    const size_t pos =
                        ((size_t)(y + 2 * (t / 3)) * PW + (gx2 + 2 * (t % 3))) * 64 + seg * 8;
                    uint4 v = *reinterpret_cast<const uint4*>(&g_xh[pos]);
                    const __half2* h = reinterpret_cast<const __half2*>(&v);
                    const float* wr = &w3s[t * 64 + seg * 8];
                    #pragma unroll
                    for (int j = 0; j < 4; j++) {
                        float2 f = __half22float2(h[j]);
                        a8[2*j]     = fmaf(f.x, wr[2*j],     a8[2*j]);
                        a8[2*j + 1] = fmaf(f.y, wr[2*j + 1], a8[2*j + 1]);
                    }
                }
                float* d = &sepi[px * EPI_STRIDE + seg * 8];
                #pragma unroll
                for (int j = 0; j < 8; j++) d[j] = a8[j];
            }
        }
        __syncthreads();

        // unified coalesced write: bias2 for sd, b3 for ~sd
        const float* arow = &sepi[m * EPI_STRIDE];
        #pragma unroll 8
        for (int c = 0; c < 64; c++) {
            const float b = sd ? __ldg(&bias[c]) : b3s[c];
            const size_t o = (size_t)c * HW + p;
            out[o] = gelu_exact(arow[c] + b) + xres[o];
        }
    }
}

// ------------------------- launch --------------------------------------------
extern "C" void kernel_launch(void* const* d_in, const int* in_sizes, int n_in,
                              void* d_out, int out_size) {
    const float* x    = (const float*)d_in[0];
    const float* mask = (const float*)d_in[1];
    const float* w1   = (const float*)d_in[2];
    const float* b1   = (const float*)d_in[3];
    const float* w2   = (const float*)d_in[4];
    const float* b2   = (const float*)d_in[5];
    const float* w3   = (const float*)d_in[6];
    const float* b3   = (const float*)d_in[7];
    float* out = (float*)d_out;

    static bool attr_set = false;
    if (!attr_set) {
        cudaFuncSetAttribute(conv_mma<1>,
            cudaFuncAttributeMaxDynamicSharedMemorySize, SM_TOTAL);
        cudaFuncSetAttribute(conv_mma<2>,
            cudaFuncAttributeMaxDynamicSharedMemorySize, SM_TOTAL);
        attr_set = true;
    }

    prep_w<<<(2 * 9 * 64 * 64 + 255) / 256, 256>>>(w1, w2);
    prep_x<<<dim3((PW + 31) / 32, PW), 256>>>(x);

    dim3 cgrid(WW / MPX, HH);   // 4 x 512

    conv_mma<1><<<cgrid, NTHR, SM_TOTAL>>>(x, b1, mask, w3, b3, out);
    conv_mma<2><<<cgrid, NTHR, SM_TOTAL>>>(x, b2, mask, w3, b3, out);
}